// round 10
// baseline (speedup 1.0000x reference)
#include <cuda_runtime.h>
#include <cuda_bf16.h>
#include <math.h>

// Problem constants
#define B      256
#define NNEG   1000
#define H      3
#define D      128
#define CMAX   250          // neg indices < min(NUM_CLUSTER) = 250
#define CPAD   256          // padded cluster dim
#define EPSF   1e-6f
#define CT     64           // c-tile width
#define BT     16           // b-tile height
#define NPROD  192          // 4 c-tiles x 16 b-tiles x 3 h
#define NGRP   16           // b-groups of 16
#define PROD_PER_GRP 12     // 4 c-tiles x 3 h

// Device globals (no allocation allowed)
__device__ float g_S[B * H * CPAD];       // sim matrix (dot+1)/2, [b][h][c]
__device__ float g_loss[B];               // per-sample loss
__device__ int   g_cntP[NGRP];            // producer arrivals per group
__device__ int   g_cntC[NGRP];            // consumer completions per group
__device__ unsigned int g_done = 0;       // global completion counter

__global__ void __launch_bounds__(256)
hirl(const float* __restrict__ se,
     const float* __restrict__ c0,
     const float* __restrict__ c1,
     const float* __restrict__ c2,
     const int* __restrict__ i2c0,
     const int* __restrict__ i2c1,
     const int* __restrict__ i2c2,
     const int* __restrict__ index,
     const int* __restrict__ neg,
     float* __restrict__ out) {
    // Producer smem
    __shared__ float cn_s[D * CT];      // raw centroid tile, [d][c] (32 KB)
    __shared__ float se_s[BT * D];      // raw se tile, [bi][d]      (8 KB)
    __shared__ float sPart[4 * CT];
    __shared__ float sInvC[CT];
    __shared__ float sInvSe[BT];
    // Consumer smem
    __shared__ float sS[H * CPAD];      // staged S row (3 KB)
    __shared__ float sPos[H];
    __shared__ int   sLab[H];
    __shared__ float rL[8];
    __shared__ float rC[8];
    __shared__ int   sLast;

    const int tid = threadIdx.x;
    const int bid = blockIdx.x;

    if (bid < NPROD) {
        // ================= PRODUCER: one sim tile =================
        const int h = bid >> 6;                  // 0..2
        const int r = bid & 63;
        const int cbase = (r & 3) * CT;          // c-tile
        const int y = r >> 2;                    // b-group 0..15
        const int b0 = y * BT;
        const float* cents = (h == 0) ? c0 : (h == 1) ? c1 : c2;

        // Load 64 centroid rows transposed into cn_s[d][c].
        for (int i = tid; i < CT * 32; i += 256) {
            int c = i & (CT - 1), dq = i >> 6;
            int cg = cbase + c;
            float4 v = make_float4(0.f, 0.f, 0.f, 0.f);
            if (cg < CMAX) v = ((const float4*)(cents + (size_t)cg * D))[dq];
            int d = dq * 4;
            cn_s[(d + 0) * CT + c] = v.x;
            cn_s[(d + 1) * CT + c] = v.y;
            cn_s[(d + 2) * CT + c] = v.z;
            cn_s[(d + 3) * CT + c] = v.w;
        }
        // Load 16 se rows [bi][d].
        for (int i = tid; i < BT * 32; i += 256) {
            int bb = i >> 5, dq = i & 31;
            float4 v = ((const float4*)(se + ((size_t)(b0 + bb) * H + h) * D))[dq];
            int d = dq * 4;
            se_s[bb * D + d + 0] = v.x;
            se_s[bb * D + d + 1] = v.y;
            se_s[bb * D + d + 2] = v.z;
            se_s[bb * D + d + 3] = v.w;
        }
        __syncthreads();

        // Centroid norm partials.
        {
            int c = tid & (CT - 1), seg = tid >> 6;
            float ss = 0.0f;
            #pragma unroll
            for (int d = seg * 32; d < seg * 32 + 32; d++) {
                float x = cn_s[d * CT + c];
                ss = fmaf(x, x, ss);
            }
            sPart[seg * CT + c] = ss;
        }
        // se norms: warp w handles rows 2w, 2w+1.
        {
            int w = tid >> 5, lane = tid & 31;
            #pragma unroll
            for (int rr = 0; rr < 2; rr++) {
                int row = w * 2 + rr;
                float4 v = ((const float4*)(se_s + row * D))[lane];
                float s = v.x * v.x + v.y * v.y + v.z * v.z + v.w * v.w;
                #pragma unroll
                for (int o = 16; o > 0; o >>= 1) s += __shfl_xor_sync(0xffffffffu, s, o);
                if (lane == 0) sInvSe[row] = 1.0f / fmaxf(sqrtf(s), 1e-12f);
            }
        }
        __syncthreads();
        if (tid < CT) {
            float ss = sPart[tid] + sPart[CT + tid] + sPart[2 * CT + tid] + sPart[3 * CT + tid];
            sInvC[tid] = 1.0f / fmaxf(sqrtf(ss), 1e-12f);
        }
        __syncthreads();

        // Main dots: thread (bi, ci) -> 4 c's.
        {
            int bi = tid >> 4, ci = tid & 15;
            int cq = ci * 4;
            float a0 = 0.f, a1 = 0.f, a2 = 0.f, a3 = 0.f;
            const float* ses = se_s + bi * D;
            #pragma unroll 8
            for (int d = 0; d < D; d++) {
                float sv = ses[d];
                float4 cv = *((const float4*)(cn_s + d * CT + cq));
                a0 = fmaf(sv, cv.x, a0);
                a1 = fmaf(sv, cv.y, a1);
                a2 = fmaf(sv, cv.z, a2);
                a3 = fmaf(sv, cv.w, a3);
            }
            float invse = sInvSe[bi];
            float4 rr;
            rr.x = (a0 * sInvC[cq + 0] * invse + 1.0f) * 0.5f;
            rr.y = (a1 * sInvC[cq + 1] * invse + 1.0f) * 0.5f;
            rr.z = (a2 * sInvC[cq + 2] * invse + 1.0f) * 0.5f;
            rr.w = (a3 * sInvC[cq + 3] * invse + 1.0f) * 0.5f;
            *((float4*)(g_S + ((size_t)(b0 + bi) * H + h) * CPAD + cbase + cq)) = rr;
        }
        __syncthreads();
        if (tid == 0) {
            __threadfence();                     // release g_S stores
            atomicAdd(&g_cntP[y], 1);
        }
        return;
    }

    // ================= CONSUMER: loss for one b =================
    const int b = bid - NPROD;
    const int grp = b >> 4;
    const int w = tid >> 5, lane = tid & 31;

    // ---- pre-wait work #1: neg triples into registers (4 per thread) ----
    int4 na, nb, nc;
    const bool on = (tid < 250);
    if (on) {
        const int4* p = (const int4*)(neg + (size_t)b * NNEG * H) + tid * 3;
        na = p[0]; nb = p[1]; nc = p[2];
    }

    // ---- pre-wait work #2: pos path (warps 0-2, h = w) ----
    if (w < H) {
        int idx = index[b];
        const int*   i2c   = (w == 0) ? i2c0 : (w == 1) ? i2c1 : i2c2;
        const float* cents = (w == 0) ? c0   : (w == 1) ? c1   : c2;
        int lab = i2c[idx];
        float4 cv = ((const float4*)(cents + (size_t)lab * D))[lane];
        float4 sv = ((const float4*)(se + ((size_t)b * H + w) * D))[lane];
        float cc = cv.x * cv.x + cv.y * cv.y + cv.z * cv.z + cv.w * cv.w;
        float ee = sv.x * sv.x + sv.y * sv.y + sv.z * sv.z + sv.w * sv.w;
        float dd = cv.x * sv.x + cv.y * sv.y + cv.z * sv.z + cv.w * sv.w;
        #pragma unroll
        for (int o = 16; o > 0; o >>= 1) {
            cc += __shfl_xor_sync(0xffffffffu, cc, o);
            ee += __shfl_xor_sync(0xffffffffu, ee, o);
            dd += __shfl_xor_sync(0xffffffffu, dd, o);
        }
        if (lane == 0) {
            float s = dd / (fmaxf(sqrtf(cc), 1e-12f) * fmaxf(sqrtf(ee), 1e-12f));
            sPos[w] = (s + 1.0f) * 0.5f;
            sLab[w] = lab;
        }
    }

    // ---- wait for this group's 12 producers ----
    if (tid == 0) {
        while (atomicAdd(&g_cntP[grp], 0) < PROD_PER_GRP) __nanosleep(64);
        __threadfence();                         // acquire
    }
    __syncthreads();

    // ---- stage S row (3 KB) ----
    if (tid < 192)
        ((float4*)sS)[tid] = ((const float4*)(g_S + (size_t)b * H * CPAD))[tid];
    __syncthreads();

    // ---- loss over 4 negatives per thread ----
    const int lab0 = sLab[0], lab1 = sLab[1], lab2 = sLab[2];
    float sumL = 0.0f, cnt = 0.0f;
    if (on) {
        int idx0[4] = { na.x, na.w, nb.z, nc.y };
        int idx1[4] = { na.y, nb.x, nb.w, nc.z };
        int idx2[4] = { na.z, nb.y, nc.x, nc.w };
        #pragma unroll
        for (int k = 0; k < 4; k++) {
            int i0 = idx0[k], i1 = idx1[k], i2 = idx2[k];
            float prod = sS[i0] * sS[CPAD + i1] * sS[2 * CPAD + i2];
            bool tn = (i0 != lab0) || (i1 != lab1) || (i2 != lab2);
            if (tn) {
                sumL += -__logf(1.0f - prod + EPSF);
                cnt  += 1.0f;
            }
        }
    }
    #pragma unroll
    for (int o = 16; o > 0; o >>= 1) {
        sumL += __shfl_xor_sync(0xffffffffu, sumL, o);
        cnt  += __shfl_xor_sync(0xffffffffu, cnt,  o);
    }
    if (lane == 0) { rL[w] = sumL; rC[w] = cnt; }
    __syncthreads();

    if (tid == 0) {
        float sL = 0.0f, sC = 0.0f;
        #pragma unroll
        for (int i = 0; i < 8; i++) { sL += rL[i]; sC += rC[i]; }
        float negl = sL / (sC + EPSF);
        float posl = -__logf(sPos[0] * sPos[1] * sPos[2] + EPSF);
        g_loss[b] = 0.5f * (posl + negl);
        __threadfence();
        // group bookkeeping: last consumer of this group resets its counters
        int c = atomicAdd(&g_cntC[grp], 1);
        if (c == 15) {
            g_cntP[grp] = 0;
            g_cntC[grp] = 0;
        }
        unsigned int t = atomicAdd(&g_done, 1u);
        sLast = (t == (unsigned)(B - 1)) ? 1 : 0;
    }
    __syncthreads();

    // ---- last consumer: deterministic final mean ----
    if (sLast) {
        __threadfence();
        float v = *((volatile float*)&g_loss[tid]);   // tid 0..255 == b
        #pragma unroll
        for (int o = 16; o > 0; o >>= 1) v += __shfl_xor_sync(0xffffffffu, v, o);
        if (lane == 0) rL[w] = v;
        __syncthreads();
        if (tid == 0) {
            float total = 0.0f;
            #pragma unroll
            for (int i = 0; i < 8; i++) total += rL[i];
            out[0] = total * (1.0f / (float)B);
            g_done = 0;   // reset for next graph replay
        }
    }
}

// ---------------------------------------------------------------------------
extern "C" void kernel_launch(void* const* d_in, const int* in_sizes, int n_in,
                              void* d_out, int out_size) {
    const float* se  = (const float*)d_in[0];
    const float* c0  = (const float*)d_in[1];
    const float* c1  = (const float*)d_in[2];
    const float* c2  = (const float*)d_in[3];
    const int* i2c0  = (const int*)d_in[4];
    const int* i2c1  = (const int*)d_in[5];
    const int* i2c2  = (const int*)d_in[6];
    const int* index = (const int*)d_in[7];
    const int* neg   = (const int*)d_in[8];
    float* out = (float*)d_out;

    hirl<<<NPROD + B, 256>>>(se, c0, c1, c2, i2c0, i2c1, i2c2, index, neg, out);
}

// round 11
// speedup vs baseline: 1.0135x; 1.0135x over previous
#include <cuda_runtime.h>
#include <cuda_fp16.h>
#include <mma.h>
#include <math.h>

// Problem constants
#define B      256
#define NNEG   1000
#define H      3
#define D      128
#define CMAX   250          // neg indices < min(NUM_CLUSTER) = 250
#define CPAD   256          // padded cluster dim
#define EPSF   1e-6f

using namespace nvcuda;

// Device globals (no allocation allowed)
__device__ float g_S[B * H * CPAD];       // sim matrix (dot+1)/2, [b][h][c]
__device__ float g_posmul[B];             // prod over h of (pos_sim+1)/2
__device__ int   g_lab[B * H];            // positive labels
__device__ float g_loss[B];               // per-sample loss
__device__ unsigned int g_done = 0;       // completion counter

// ---------------------------------------------------------------------------
// K1: tensor-core sim + pos-path precompute.
//     grid = (4, 4, 4), block = 256 (8 warps).
//       z<3  : one 64b x 64c tile for hierarchy z via wmma (fp16 in, fp32 acc)
//       z==3 : 16 pos-path blocks, each covers 16 b's (validated R9 pattern)
// ---------------------------------------------------------------------------
__global__ void __launch_bounds__(256)
k_sim(const float* __restrict__ se,
      const float* __restrict__ c0,
      const float* __restrict__ c1,
      const float* __restrict__ c2,
      const int* __restrict__ i2c0,
      const int* __restrict__ i2c1,
      const int* __restrict__ i2c2,
      const int* __restrict__ index) {
    __shared__ __align__(32) __half A_s[64 * 128];   // se tile fp16 (16 KB)
    __shared__ __align__(32) __half B_s[64 * 128];   // centroid tile fp16 (16 KB)
    __shared__ float invSe_s[64];
    __shared__ float invC_s[64];

    const int tid  = threadIdx.x;
    const int w    = tid >> 5;
    const int lane = tid & 31;

    if (blockIdx.z == 3) {
        // ---- pos path: 16 blocks, warp w handles b = id*16 + w*2 + r ----
        int id = blockIdx.y * 4 + blockIdx.x;   // 0..15
        #pragma unroll
        for (int r = 0; r < 2; r++) {
            int b = id * 16 + w * 2 + r;
            int idx = index[b];
            int lab0 = i2c0[idx], lab1 = i2c1[idx], lab2 = i2c2[idx];
            float4 cv0 = ((const float4*)(c0 + (size_t)lab0 * D))[lane];
            float4 cv1 = ((const float4*)(c1 + (size_t)lab1 * D))[lane];
            float4 cv2 = ((const float4*)(c2 + (size_t)lab2 * D))[lane];
            float4 sv0 = ((const float4*)(se + ((size_t)b * H + 0) * D))[lane];
            float4 sv1 = ((const float4*)(se + ((size_t)b * H + 1) * D))[lane];
            float4 sv2 = ((const float4*)(se + ((size_t)b * H + 2) * D))[lane];

            float prod = 1.0f;
            #pragma unroll
            for (int h = 0; h < H; h++) {
                float4 cv = (h == 0) ? cv0 : (h == 1) ? cv1 : cv2;
                float4 sv = (h == 0) ? sv0 : (h == 1) ? sv1 : sv2;
                float cc = cv.x * cv.x + cv.y * cv.y + cv.z * cv.z + cv.w * cv.w;
                float ee = sv.x * sv.x + sv.y * sv.y + sv.z * sv.z + sv.w * sv.w;
                float dd = cv.x * sv.x + cv.y * sv.y + cv.z * sv.z + cv.w * sv.w;
                #pragma unroll
                for (int o = 16; o > 0; o >>= 1) {
                    cc += __shfl_xor_sync(0xffffffffu, cc, o);
                    ee += __shfl_xor_sync(0xffffffffu, ee, o);
                    dd += __shfl_xor_sync(0xffffffffu, dd, o);
                }
                float s = dd / (fmaxf(sqrtf(cc), 1e-12f) * fmaxf(sqrtf(ee), 1e-12f));
                prod *= (s + 1.0f) * 0.5f;
            }
            if (lane == 0) {
                g_posmul[b] = prod;
                g_lab[b * H + 0] = lab0;
                g_lab[b * H + 1] = lab1;
                g_lab[b * H + 2] = lab2;
            }
        }
        return;
    }

    // ---- sim tile: 64 b's x 64 c's for hierarchy h ----
    const int h = blockIdx.z;
    const int cbase = blockIdx.x * 64;
    const int b0 = blockIdx.y * 64;
    const float* cents = (h == 0) ? c0 : (h == 1) ? c1 : c2;

    // Load + convert A (se) rows: warp w handles rows w*8 .. w*8+7.
    #pragma unroll
    for (int rr = 0; rr < 8; rr++) {
        int row = w * 8 + rr;
        float4 v = ((const float4*)(se + ((size_t)(b0 + row) * H + h) * D))[lane];
        float ss = v.x * v.x + v.y * v.y + v.z * v.z + v.w * v.w;
        #pragma unroll
        for (int o = 16; o > 0; o >>= 1) ss += __shfl_xor_sync(0xffffffffu, ss, o);
        if (lane == 0) invSe_s[row] = 1.0f / fmaxf(sqrtf(ss), 1e-12f);
        __half2* dst = (__half2*)(A_s + row * 128 + lane * 4);
        dst[0] = __floats2half2_rn(v.x, v.y);
        dst[1] = __floats2half2_rn(v.z, v.w);
    }
    // Load + convert B (centroid) rows.
    #pragma unroll
    for (int rr = 0; rr < 8; rr++) {
        int row = w * 8 + rr;
        int c = cbase + row;
        float4 v = make_float4(0.f, 0.f, 0.f, 0.f);
        if (c < CMAX) v = ((const float4*)(cents + (size_t)c * D))[lane];
        float ss = v.x * v.x + v.y * v.y + v.z * v.z + v.w * v.w;
        #pragma unroll
        for (int o = 16; o > 0; o >>= 1) ss += __shfl_xor_sync(0xffffffffu, ss, o);
        if (lane == 0)
            invC_s[row] = (c < CMAX) ? 1.0f / fmaxf(sqrtf(ss), 1e-12f) : 0.0f;
        __half2* dst = (__half2*)(B_s + row * 128 + lane * 4);
        dst[0] = __floats2half2_rn(v.x, v.y);
        dst[1] = __floats2half2_rn(v.z, v.w);
    }
    __syncthreads();

    // wmma: warp w -> b-tile (w>>1), c-tiles (w&1)*2 + {0,1}. 16x16x16, K=8 steps.
    const int btl = w >> 1;
    const int ctp = (w & 1) * 2;
    wmma::fragment<wmma::accumulator, 16, 16, 16, float> fc0, fc1;
    wmma::fill_fragment(fc0, 0.0f);
    wmma::fill_fragment(fc1, 0.0f);
    {
        wmma::fragment<wmma::matrix_a, 16, 16, 16, __half, wmma::row_major> fa;
        wmma::fragment<wmma::matrix_b, 16, 16, 16, __half, wmma::col_major> fb;
        #pragma unroll
        for (int k = 0; k < 8; k++) {
            wmma::load_matrix_sync(fa, A_s + (btl * 16) * 128 + k * 16, 128);
            wmma::load_matrix_sync(fb, B_s + (ctp * 16) * 128 + k * 16, 128);
            wmma::mma_sync(fc0, fa, fb, fc0);
            wmma::load_matrix_sync(fb, B_s + ((ctp + 1) * 16) * 128 + k * 16, 128);
            wmma::mma_sync(fc1, fa, fb, fc1);
        }
    }
    __syncthreads();                 // everyone done reading A_s/B_s

    // Reuse A_s as the fp32 C tile (64x64 floats = 16 KB, exact fit).
    float* C_s = (float*)A_s;
    wmma::store_matrix_sync(C_s + (btl * 16) * 64 + ctp * 16, fc0, 64,
                            wmma::mem_row_major);
    wmma::store_matrix_sync(C_s + (btl * 16) * 64 + (ctp + 1) * 16, fc1, 64,
                            wmma::mem_row_major);
    __syncthreads();

    // Scale + write: 1024 float4 chunks, 4 per thread.
    #pragma unroll
    for (int k = 0; k < 4; k++) {
        int i = tid + k * 256;
        int bi = i >> 4;             // row (b-local)
        int ci = (i & 15) * 4;       // col base (c-local)
        float4 v = ((const float4*)C_s)[i];
        float is = invSe_s[bi];
        v.x = (v.x * is * invC_s[ci + 0] + 1.0f) * 0.5f;
        v.y = (v.y * is * invC_s[ci + 1] + 1.0f) * 0.5f;
        v.z = (v.z * is * invC_s[ci + 2] + 1.0f) * 0.5f;
        v.w = (v.w * is * invC_s[ci + 3] + 1.0f) * 0.5f;
        *((float4*)(g_S + ((size_t)(b0 + bi) * H + h) * CPAD + cbase + ci)) = v;
    }
}

// ---------------------------------------------------------------------------
// K2: per-b loss, 256 threads, 4 negs/thread, ONE log per thread
//     (product of masked (1-p+eps) terms; >= 1e-24, no underflow).
// ---------------------------------------------------------------------------
__global__ void __launch_bounds__(256)
k_loss(const int* __restrict__ neg, float* __restrict__ out) {
    __shared__ float sS[H * CPAD];    // staged S row (3 KB)
    __shared__ float rL[8];
    __shared__ float rC[8];
    __shared__ int   sLast;

    const int b = blockIdx.x, tid = threadIdx.x;
    const int w = tid >> 5, lane = tid & 31;

    // neg triples into registers (4 per thread via 3 x int4).
    int4 na, nb, nc;
    const bool on = (tid < 250);
    if (on) {
        const int4* p = ((const int4*)(neg + (size_t)b * NNEG * H)) + tid * 3;
        na = p[0]; nb = p[1]; nc = p[2];
    }
    // Stage S row.
    if (tid < 192)
        ((float4*)sS)[tid] = ((const float4*)(g_S + (size_t)b * H * CPAD))[tid];
    __syncthreads();

    const int lab0 = g_lab[b * H + 0];
    const int lab1 = g_lab[b * H + 1];
    const int lab2 = g_lab[b * H + 2];

    float prodv = 1.0f, cnt = 0.0f;
    if (on) {
        int idx0[4] = { na.x, na.w, nb.z, nc.y };
        int idx1[4] = { na.y, nb.x, nb.w, nc.z };
        int idx2[4] = { na.z, nb.y, nc.x, nc.w };
        #pragma unroll
        for (int k = 0; k < 4; k++) {
            int i0 = idx0[k], i1 = idx1[k], i2 = idx2[k];
            float p = sS[i0] * sS[CPAD + i1] * sS[2 * CPAD + i2];
            bool tn = (i0 != lab0) || (i1 != lab1) || (i2 != lab2);
            if (tn) {
                prodv *= (1.0f - p + EPSF);
                cnt   += 1.0f;
            }
        }
    }
    float sumL = -__logf(prodv);     // == sum over this thread's negs of -log(.)
    #pragma unroll
    for (int o = 16; o > 0; o >>= 1) {
        sumL += __shfl_xor_sync(0xffffffffu, sumL, o);
        cnt  += __shfl_xor_sync(0xffffffffu, cnt,  o);
    }
    if (lane == 0) { rL[w] = sumL; rC[w] = cnt; }
    __syncthreads();

    if (tid == 0) {
        float sL = 0.0f, sC = 0.0f;
        #pragma unroll
        for (int i = 0; i < 8; i++) { sL += rL[i]; sC += rC[i]; }
        float negl = sL / (sC + EPSF);
        float posl = -__logf(g_posmul[b] + EPSF);
        g_loss[b] = 0.5f * (posl + negl);
        __threadfence();
        unsigned int t = atomicAdd(&g_done, 1u);
        sLast = (t == gridDim.x - 1) ? 1 : 0;
    }
    __syncthreads();

    // Last block: deterministic final mean over B=256 losses.
    if (sLast) {
        __threadfence();
        float v = *((volatile float*)&g_loss[tid]);    // tid 0..255 == b
        #pragma unroll
        for (int o = 16; o > 0; o >>= 1) v += __shfl_xor_sync(0xffffffffu, v, o);
        if (lane == 0) rL[w] = v;
        __syncthreads();
        if (tid == 0) {
            float total = 0.0f;
            #pragma unroll
            for (int i = 0; i < 8; i++) total += rL[i];
            out[0] = total * (1.0f / (float)B);
            g_done = 0;   // reset for next graph replay
        }
    }
}

// ---------------------------------------------------------------------------
extern "C" void kernel_launch(void* const* d_in, const int* in_sizes, int n_in,
                              void* d_out, int out_size) {
    const float* se  = (const float*)d_in[0];
    const float* c0  = (const float*)d_in[1];
    const float* c1  = (const float*)d_in[2];
    const float* c2  = (const float*)d_in[3];
    const int* i2c0  = (const int*)d_in[4];
    const int* i2c1  = (const int*)d_in[5];
    const int* i2c2  = (const int*)d_in[6];
    const int* index = (const int*)d_in[7];
    const int* neg   = (const int*)d_in[8];
    float* out = (float*)d_out;

    k_sim<<<dim3(4, 4, 4), 256>>>(se, c0, c1, c2, i2c0, i2c1, i2c2, index);
    k_loss<<<B, 256>>>(neg, out);
}